// round 14
// baseline (speedup 1.0000x reference)
#include <cuda_runtime.h>
#include <cstdint>

// DetectionFocalLoss — single-kernel, warp-transposed class loop,
// division-free IoU classification, raw-lg2 focal accumulation.
//   d_in[0] classifications float32 (B,N,C)
//   d_in[1] regressions     float32 (B,N,4)
//   d_in[2] anchors         float32 (1,N,4)  [cx,cy,w,h]
//   d_in[3] annotations     float32 (B,M,5)  [x1,y1,x2,y2,cls]
// Output: float32[2]

#define TPB 256
#define NBMAX 4096
#define BMAX 16
#define MMAX 128

__device__ float g_pcl[BMAX * NBMAX];
__device__ float g_psl[BMAX * NBMAX];
__device__ float g_pct[BMAX * NBMAX];
__device__ unsigned g_done = 0;

__device__ __forceinline__ float clip_cls(float x) {
    return fminf(fmaxf(x, 1e-4f), 1.0f - 1e-4f);
}

// raw label-0 focal term: xc^2 * lg2(1-xc)   (negative; scaled by -0.75*ln2 later)
__device__ __forceinline__ float fn_raw(float x) {
    float xc = clip_cls(x);
    return xc * xc * __log2f(1.0f - xc);
}

#define K_NEG075LN2 (-0.5198603854199589f)   // -0.75*ln2
#define K_NEG025LN2 (-0.1732867951399863f)   // -0.25*ln2

template <int C4_CT>
__global__ __launch_bounds__(TPB)
void fused_kernel(const float* __restrict__ cls_,
                  const float* __restrict__ reg_,
                  const float* __restrict__ anc,
                  const float* __restrict__ ann,
                  float* __restrict__ out,
                  int N, int c4_rt, int M, int NB, int B)
{
    const int C4 = (C4_CT > 0) ? C4_CT : c4_rt;
    const int C  = C4 * 4;

    __shared__ float4 s_box[MMAX];
    __shared__ float  s_areaB[MMAX];
    __shared__ float  s_cid[MMAX];
    __shared__ float  w_cl[8], w_sl[8], w_ct[8];
    __shared__ unsigned s_rank;
    __shared__ float  f_cls[BMAX], f_es[BMAX], f_ec[BMAX];

    const int b    = blockIdx.y;
    const int tid  = threadIdx.x;
    const int ww   = tid >> 5;
    const int lane = tid & 31;
    const int nb   = (blockIdx.x * 8 + ww) * 32;   // warp's first anchor
    const int n    = nb + lane;

    if (tid < M) {
        const float* ap = ann + ((size_t)b * M + tid) * 5;
        float x1 = ap[0], y1 = ap[1], x2 = ap[2], y2 = ap[3];
        s_box[tid]   = make_float4(x1, y1, x2, y2);
        s_areaB[tid] = (x2 - x1) * (y2 - y1);
        s_cid[tid]   = ap[4];
    }
    __syncthreads();

    // ---- division-free pos/neg classification ----
    float4 a = make_float4(0.f, 0.f, 1.f, 1.f);
    float t0 = 0.f, t1 = 0.f, t2 = 0.f, t3 = 0.f, area_a = 0.f;
    bool pos = false, valid = false;
    if (n < N) {
        a = reinterpret_cast<const float4*>(anc)[n];
        t0 = a.x - a.z * 0.5f;
        t1 = a.y - a.w * 0.5f;
        t2 = a.x + a.z * 0.5f;
        t3 = a.y + a.w * 0.5f;
        area_a = (t2 - t0) * (t3 - t1);

        float p1 = -1e30f, p2 = -1e30f;
        #pragma unroll 4
        for (int m = 0; m < M; m++) {
            float4 bx = s_box[m];
            float lx = fmaxf(t0, bx.x), ly = fmaxf(t1, bx.y);
            float rx = fminf(t2, bx.z), ry = fminf(t3, bx.w);
            float wi = fmaxf(rx - lx, 0.0f);
            float hi = fmaxf(ry - ly, 0.0f);
            float inter = wi * hi;
            float sum = area_a + s_areaB[m];
            p1 = fmaxf(p1, fmaf(3.0f, inter, -sum));   // >=0  <=> iou >= 0.5
            p2 = fmaxf(p2, fmaf(3.5f, inter, -sum));   // <=0  <=> max iou <= 0.4
        }
        pos   = (p1 >= 0.0f);
        valid = pos || (p2 <= 0.0f);
    }
    const unsigned vm = __ballot_sync(0xFFFFFFFFu, valid);

    // ---- warp-transposed coalesced class-loss raw sum ----
    float craw = 0.0f;   // sum of xc^2*lg2(1-xc) over valid rows
    if (nb < N) {
        const float4* p4 =
            reinterpret_cast<const float4*>(cls_ + ((size_t)b * N + nb) * C);
        if (nb + 32 <= N) {
            #pragma unroll
            for (int j = 0; j < C4; j++) {
                int k = j * 32 + lane;
                int r = k / C4;
                float4 v = p4[k];
                float t = fn_raw(v.x) + fn_raw(v.y) + fn_raw(v.z) + fn_raw(v.w);
                craw += ((vm >> r) & 1u) ? t : 0.0f;
            }
        } else {
            for (int j = 0; j < C4; j++) {
                int k = j * 32 + lane;
                int r = k / C4;
                if ((nb + r) < N && ((vm >> r) & 1u)) {
                    float4 v = p4[k];
                    craw += fn_raw(v.x) + fn_raw(v.y) + fn_raw(v.z) + fn_raw(v.w);
                }
            }
        }
    }

    // ---- rare positive-anchor path: exact argmax + corrections + smooth-L1 ----
    float cfix = 0.0f, sl = 0.0f, ctf = 0.0f;
    if (pos) {
        ctf = 1.0f;
        // exact argmax with the reference's iou formula (first-max semantics)
        float best = -1.0f;
        int bi = 0;
        for (int m = 0; m < M; m++) {
            float4 bx = s_box[m];
            float lx = fmaxf(t0, bx.x), ly = fmaxf(t1, bx.y);
            float rx = fminf(t2, bx.z), ry = fminf(t3, bx.w);
            float wi = fmaxf(rx - lx, 0.0f);
            float hi = fmaxf(ry - ly, 0.0f);
            float inter = wi * hi;
            float uni = area_a + s_areaB[m] - inter;
            float iou = inter / fmaxf(uni, 1e-8f);
            if (iou > best) { best = iou; bi = m; }
        }

        const float* cp = cls_ + ((size_t)b * N + n) * C;
        int cid = (int)s_cid[bi];
        float x = clip_cls(cp[cid]);
        craw -= x * x * __log2f(1.0f - x);              // remove label-0 raw term
        float om = 1.0f - x;
        cfix += om * om * __log2f(x) * K_NEG025LN2;     // add label-1 term

        float4 r = reinterpret_cast<const float4*>(reg_)[(size_t)b * N + n];
        float4 g = s_box[bi];
        float dw  = g.z - g.x;
        float dh  = g.w - g.y;
        float dxc = g.x + g.z * 0.5f;   // replicate reference exactly
        float dyc = g.y + g.w * 0.5f;
        float dx  = (dxc - a.x) / a.z;
        float dy  = (dyc - a.y) / a.w;
        float dwl = __logf(dw / a.z);
        float dhl = __logf(dh / a.w);
        float d0 = fabsf(r.x / 0.1f - dx  / 0.1f);
        float d1 = fabsf(r.y / 0.1f - dy  / 0.1f);
        float d2 = fabsf(r.z / 0.2f - dwl / 0.2f);
        float d3 = fabsf(r.w / 0.2f - dhl / 0.2f);
        float s0 = (d0 < 1.0f) ? 0.5f * d0 * d0 : d0 - 0.5f;
        float s1 = (d1 < 1.0f) ? 0.5f * d1 * d1 : d1 - 0.5f;
        float s2 = (d2 < 1.0f) ? 0.5f * d2 * d2 : d2 - 0.5f;
        float s3 = (d3 < 1.0f) ? 0.5f * d3 * d3 : d3 - 0.5f;
        sl = s0 + s1 + s2 + s3;
    }

    // per-lane class loss: apply uniform constant once
    float cl = fmaf(craw, K_NEG075LN2, cfix);

    // ---- deterministic warp xor-tree reduction ----
    #pragma unroll
    for (int o = 16; o > 0; o >>= 1) {
        cl  += __shfl_xor_sync(0xFFFFFFFFu, cl,  o);
        sl  += __shfl_xor_sync(0xFFFFFFFFu, sl,  o);
        ctf += __shfl_xor_sync(0xFFFFFFFFu, ctf, o);
    }
    if (lane == 0) { w_cl[ww] = cl; w_sl[ww] = sl; w_ct[ww] = ctf; }
    __syncthreads();

    if (tid == 0) {
        float acl = 0.f, asl = 0.f, act = 0.f;
        #pragma unroll
        for (int i = 0; i < 8; i++) { acl += w_cl[i]; asl += w_sl[i]; act += w_ct[i]; }
        int p = b * NB + blockIdx.x;
        g_pcl[p] = acl;
        g_psl[p] = asl;
        g_pct[p] = act;
        __threadfence();
        s_rank = atomicAdd(&g_done, 1u);
    }
    __syncthreads();

    // ---- last block finalizes ----
    if (s_rank == (unsigned)(NB * B) - 1u) {
        __threadfence();
        for (int bb = ww; bb < B; bb += 8) {
            float cl2 = 0.f, sl2 = 0.f, ct2 = 0.f;
            for (int i = lane; i < NB; i += 32) {
                cl2 += g_pcl[bb * NB + i];
                sl2 += g_psl[bb * NB + i];
                ct2 += g_pct[bb * NB + i];
            }
            #pragma unroll
            for (int o = 16; o > 0; o >>= 1) {
                cl2 += __shfl_xor_sync(0xFFFFFFFFu, cl2, o);
                sl2 += __shfl_xor_sync(0xFFFFFFFFu, sl2, o);
                ct2 += __shfl_xor_sync(0xFFFFFFFFu, ct2, o);
            }
            if (lane == 0) {
                float denom    = fmaxf(ct2, 1.0f);
                float cls_loss = cl2 / denom;
                float reg_mean = sl2 / (denom * 4.0f);
                bool  has_pos  = (ct2 > 0.0f);
                f_cls[bb] = cls_loss;
                f_es[bb]  = has_pos ? (reg_mean / denom + reg_mean) : 0.0f;
                f_ec[bb]  = has_pos ? 2.0f : 1.0f;
            }
        }
        __syncthreads();
        if (tid == 0) {
            float acl = 0.f, aes = 0.f, aec = 0.f;
            for (int i = 0; i < B; i++) { acl += f_cls[i]; aes += f_es[i]; aec += f_ec[i]; }
            out[0] = acl / (float)B;
            out[1] = aes / aec;
            g_done = 0;   // reset for graph replay
        }
    }
}

extern "C" void kernel_launch(void* const* d_in, const int* in_sizes, int n_in,
                              void* d_out, int out_size)
{
    const float* cls_ = (const float*)d_in[0];
    const float* reg_ = (const float*)d_in[1];
    const float* anc  = (const float*)d_in[2];
    const float* ann  = (const float*)d_in[3];
    float* out = (float*)d_out;

    int N = in_sizes[2] / 4;
    int B = in_sizes[1] / (N * 4);
    int C = in_sizes[0] / (B * N);
    int M = in_sizes[3] / (B * 5);

    int NB = (N + TPB - 1) / TPB;

    dim3 grid(NB, B);
    if (C == 80) {
        fused_kernel<20><<<grid, TPB>>>(cls_, reg_, anc, ann, out, N, C / 4, M, NB, B);
    } else {
        fused_kernel<0><<<grid, TPB>>>(cls_, reg_, anc, ann, out, N, C / 4, M, NB, B);
    }
}